// round 10
// baseline (speedup 1.0000x reference)
#include <cuda_runtime.h>

#define NUM_NODES 50000
#define C 64
#define NUM_EDGES 800000

// Scratch (allocation-free rule: __device__ globals)
// One extra trash row at the end: invalid edges RED into it harmlessly.
__device__ __align__(16) float g_aggr[(NUM_NODES + 1) * C];
__device__ float g_deg[NUM_NODES];
__device__ __align__(16) float g_Wt[128 * 64];   // W transposed: [k][o]
__device__ __align__(8) int2 g_edges[NUM_EDGES]; // {row*256, col*256} byte offsets

// ---------------------------------------------------------------------------
// Kernel 1: PACK — per-block dtype detect, precompute per-edge byte offsets,
// count degrees. First 32 blocks also transpose W. Grid 3125 x 256 = edges.
// Row-half int64 view is in-bounds for both widths (validated R7).
// ---------------------------------------------------------------------------
__global__ void pack_kernel(const void* __restrict__ ei_raw,
                            const float* __restrict__ W) {
    int e = blockIdx.x * 256 + threadIdx.x;

    // W transpose piggyback (blocks 0..31)
    if (e < 64 * 128) {
        int o = e >> 7;
        int k = e & 127;
        g_Wt[k * 64 + o] = W[e];
    }

    const long long* ei64 = (const long long*)ei_raw;
    long long rv = ei64[e];   // row half: safe read for both dtypes
    int is64 = __syncthreads_and(rv >= 0 && rv < NUM_NODES);

    long long r, c;
    if (is64) {
        r = rv;
        c = ei64[NUM_EDGES + e];
    } else {
        const int* ei = (const int*)ei_raw;
        r = ei[e];
        c = ei[NUM_EDGES + e];
    }
    bool ok = (r >= 0 && r < NUM_NODES && c >= 0 && c < NUM_NODES);
    int roff = ok ? (int)r * 256 : 0;                 // byte offset into x
    int coff = ok ? (int)c * 256 : NUM_NODES * 256;   // byte offset into aggr (trash row if bad)
    g_edges[e] = make_int2(roff, coff);
    if (ok) atomicAdd(&g_deg[(int)c], 1.0f);
}

// ---------------------------------------------------------------------------
// Kernel 2: SLIM scatter — 16 lanes/edge (validated layout), minimal body:
// broadcast int2 offset load, LDG.128 gather, RED.128. No branches, no
// bounds checks, no deg atomic (all moved to pack). Grid exact: 50000 x 256.
// ---------------------------------------------------------------------------
__global__ void scatter_kernel(const float* __restrict__ x) {
    int idx = blockIdx.x * 256 + threadIdx.x;
    int e     = idx >> 4;
    int chunk = idx & 15;

    int2 off = __ldg(&g_edges[e]);   // 16 lanes same addr -> broadcast

    float4 v = __ldg((const float4*)((const char*)x + off.x) + chunk);
    float* dst = (float*)((char*)g_aggr + off.y) + (chunk << 2);
    asm volatile("red.global.add.v4.f32 [%0], {%1,%2,%3,%4};"
                 :: "l"(dst), "f"(v.x), "f"(v.y), "f"(v.z), "f"(v.w)
                 : "memory");
}

// ---------------------------------------------------------------------------
// Kernel 3 (validated R4/R9 form): out[n] = concat(x[n], aggr[n]*rdeg)@W^T + b
// 64 nodes x 64 outs per 256-thread block; thread = 1 node x 16 outs
// (8 f32x2 accumulators, fma.rn.f32x2). Measured ~35 us.
// ---------------------------------------------------------------------------
#define WT_STRIDE 64
#define F_STRIDE  65
#define SMEM_WT   0
#define SMEM_F    (128 * WT_STRIDE)                 // floats
#define SMEM_RD   (SMEM_F + 128 * F_STRIDE)         // floats
#define GEMM_SMEM ((SMEM_RD + 64) * 4)              // bytes = 66304

__global__ void __launch_bounds__(256, 3)
gemm_kernel(const float* __restrict__ x,
            const float* __restrict__ b,
            float* __restrict__ out) {
    extern __shared__ float sm[];
    float* Wt   = sm + SMEM_WT;   // [k][o] stride 64
    float* F    = sm + SMEM_F;    // [k][n] stride 65
    float* rdeg = sm + SMEM_RD;   // [64]

    int t = threadIdx.x;
    int base = blockIdx.x * 64;

    // Stage W: straight copy (coalesced LDG.128, conflict-free STS.128)
    #pragma unroll
    for (int i = t; i < 128 * 64 / 4; i += 256) {
        ((float4*)Wt)[i] = ((const float4*)g_Wt)[i];
    }

    // Per-node reciprocal degree
    if (t < 64) {
        int n = base + t;
        rdeg[t] = (n < NUM_NODES) ? __frcp_rn(fmaxf(g_deg[n], 1.0f)) : 0.0f;
    }
    __syncthreads();

    // Stage features transposed: F[c][n]; coalesced gmem reads,
    // STS stride 65 -> conflict-free.
    #pragma unroll
    for (int i = t; i < 64 * 128; i += 256) {
        int nl = i >> 7;
        int c  = i & 127;
        int n  = base + nl;
        float v = 0.0f;
        if (n < NUM_NODES) {
            v = (c < C) ? x[n * C + c]
                        : g_aggr[n * C + (c - C)] * rdeg[nl];
        }
        F[c * F_STRIDE + nl] = v;
    }
    __syncthreads();

    int nl = t & 63;          // node within block
    int o0 = (t >> 6) << 4;   // output base: 0,16,32,48 (warp-uniform)
    int n  = base + nl;

    // 8 packed f32x2 accumulators = 16 outputs
    unsigned long long acc[8];
    #pragma unroll
    for (int p = 0; p < 8; p++) acc[p] = 0ULL;

    const float* frow = F + nl;
    const float* wrow = Wt + o0;

    #pragma unroll 8
    for (int k = 0; k < 128; k++) {
        float f = frow[k * F_STRIDE];
        unsigned long long fp;
        asm("mov.b64 %0, {%1, %1};" : "=l"(fp) : "f"(f));
        const ulonglong2* wv = (const ulonglong2*)(wrow + k * WT_STRIDE);
        ulonglong2 w01 = wv[0];
        ulonglong2 w23 = wv[1];
        ulonglong2 w45 = wv[2];
        ulonglong2 w67 = wv[3];
        asm("fma.rn.f32x2 %0, %1, %2, %0;" : "+l"(acc[0]) : "l"(w01.x), "l"(fp));
        asm("fma.rn.f32x2 %0, %1, %2, %0;" : "+l"(acc[1]) : "l"(w01.y), "l"(fp));
        asm("fma.rn.f32x2 %0, %1, %2, %0;" : "+l"(acc[2]) : "l"(w23.x), "l"(fp));
        asm("fma.rn.f32x2 %0, %1, %2, %0;" : "+l"(acc[3]) : "l"(w23.y), "l"(fp));
        asm("fma.rn.f32x2 %0, %1, %2, %0;" : "+l"(acc[4]) : "l"(w45.x), "l"(fp));
        asm("fma.rn.f32x2 %0, %1, %2, %0;" : "+l"(acc[5]) : "l"(w45.y), "l"(fp));
        asm("fma.rn.f32x2 %0, %1, %2, %0;" : "+l"(acc[6]) : "l"(w67.x), "l"(fp));
        asm("fma.rn.f32x2 %0, %1, %2, %0;" : "+l"(acc[7]) : "l"(w67.y), "l"(fp));
    }

    if (n >= NUM_NODES) return;

    // Unpack, add bias, store as 4 x STG.128
    float* orow = out + n * 64 + o0;
    #pragma unroll
    for (int j = 0; j < 4; j++) {
        float lo0, hi0, lo1, hi1;
        asm("mov.b64 {%0, %1}, %2;" : "=f"(lo0), "=f"(hi0) : "l"(acc[2 * j]));
        asm("mov.b64 {%0, %1}, %2;" : "=f"(lo1), "=f"(hi1) : "l"(acc[2 * j + 1]));
        float4 r;
        r.x = lo0 + b[o0 + 4 * j + 0];
        r.y = hi0 + b[o0 + 4 * j + 1];
        r.z = lo1 + b[o0 + 4 * j + 2];
        r.w = hi1 + b[o0 + 4 * j + 3];
        *(float4*)(orow + 4 * j) = r;
    }
}

// ---------------------------------------------------------------------------
extern "C" void kernel_launch(void* const* d_in, const int* in_sizes, int n_in,
                              void* d_out, int out_size) {
    const float* x   = (const float*)d_in[0];
    const void*  ei  = d_in[1];
    const float* W   = (const float*)d_in[2];
    const float* b   = (const float*)d_in[3];
    float*       out = (float*)d_out;

    cudaFuncSetAttribute(gemm_kernel,
                         cudaFuncAttributeMaxDynamicSharedMemorySize, GEMM_SMEM);

    // Zero scratch via graph memset nodes (capture-legal, no allocation).
    void* aggr_ptr = nullptr;
    void* deg_ptr  = nullptr;
    cudaGetSymbolAddress(&aggr_ptr, g_aggr);
    cudaGetSymbolAddress(&deg_ptr, g_deg);
    cudaMemsetAsync(aggr_ptr, 0, NUM_NODES * C * sizeof(float));
    cudaMemsetAsync(deg_ptr, 0, NUM_NODES * sizeof(float));

    pack_kernel<<<NUM_EDGES / 256, 256>>>(ei, W);
    scatter_kernel<<<(NUM_EDGES * 16) / 256, 256>>>(x);
    gemm_kernel<<<(NUM_NODES + 63) / 64, 256, GEMM_SMEM>>>(x, b, out);
}

// round 11
// speedup vs baseline: 1.1503x; 1.1503x over previous
#include <cuda_runtime.h>

#define NUM_NODES 50000
#define C 64
#define NUM_EDGES 800000
#define HALF_E (NUM_EDGES / 2)

// Scratch (allocation-free rule: __device__ globals)
// One extra trash row: invalid edges RED into it harmlessly.
__device__ __align__(16) float g_aggr[(NUM_NODES + 1) * C];
__device__ float g_deg[NUM_NODES];
__device__ __align__(16) float g_Wt[128 * 64];    // W transposed: [k][o]
__device__ __align__(16) int2 g_edges[NUM_EDGES]; // {row*256, col*256} byte offsets

// ---------------------------------------------------------------------------
// s2 Kernel: transpose W [o][k] -> g_Wt [k][o]. 32 blocks x 256.
// ---------------------------------------------------------------------------
__global__ void wprep_kernel(const float* __restrict__ W) {
    int i = blockIdx.x * 256 + threadIdx.x;
    if (i < 64 * 128) {
        int o = i >> 7;
        int k = i & 127;
        g_Wt[k * 64 + o] = W[i];
    }
}

// ---------------------------------------------------------------------------
// Kernel: PACK (vectorized, 2 edges/thread). Per-block dtype detect via
// int64 view of the row half (in-bounds for both widths). Grid 625 x 640.
// ---------------------------------------------------------------------------
__global__ void pack_kernel(const void* __restrict__ ei_raw) {
    int t = blockIdx.x * 640 + threadIdx.x;   // [0, HALF_E)

    const long long* ei64 = (const long long*)ei_raw;
    longlong2 rv = __ldg((const longlong2*)ei64 + t);   // edges 2t, 2t+1 row half
    bool in0 = (rv.x >= 0 && rv.x < NUM_NODES);
    bool in1 = (rv.y >= 0 && rv.y < NUM_NODES);
    int is64 = __syncthreads_and(in0 && in1);

    long long r0, r1, c0, c1;
    if (is64) {
        r0 = rv.x; r1 = rv.y;
        longlong2 cv = __ldg((const longlong2*)(ei64 + NUM_EDGES) + t);
        c0 = cv.x; c1 = cv.y;
    } else {
        const int* ei = (const int*)ei_raw;
        int2 rv32 = __ldg((const int2*)ei + t);
        r0 = rv32.x; r1 = rv32.y;
        int2 cv32 = __ldg((const int2*)(ei + NUM_EDGES) + t);
        c0 = cv32.x; c1 = cv32.y;
    }
    bool ok0 = (r0 >= 0 && r0 < NUM_NODES && c0 >= 0 && c0 < NUM_NODES);
    bool ok1 = (r1 >= 0 && r1 < NUM_NODES && c1 >= 0 && c1 < NUM_NODES);

    int4 pk;
    pk.x = ok0 ? (int)r0 * 256 : 0;
    pk.y = ok0 ? (int)c0 * 256 : NUM_NODES * 256;
    pk.z = ok1 ? (int)r1 * 256 : 0;
    pk.w = ok1 ? (int)c1 * 256 : NUM_NODES * 256;
    ((int4*)g_edges)[t] = pk;

    if (ok0) atomicAdd(&g_deg[(int)c0], 1.0f);
    if (ok1) atomicAdd(&g_deg[(int)c1], 1.0f);
}

// ---------------------------------------------------------------------------
// Kernel: SLIM scatter (validated R10 form) — 16 lanes/edge, branch-free.
// ---------------------------------------------------------------------------
__global__ void scatter_kernel(const float* __restrict__ x) {
    int idx = blockIdx.x * 256 + threadIdx.x;
    int e     = idx >> 4;
    int chunk = idx & 15;

    int2 off = __ldg(&g_edges[e]);   // 16 lanes same addr -> broadcast

    float4 v = __ldg((const float4*)((const char*)x + off.x) + chunk);
    float* dst = (float*)((char*)g_aggr + off.y) + (chunk << 2);
    asm volatile("red.global.add.v4.f32 [%0], {%1,%2,%3,%4};"
                 :: "l"(dst), "f"(v.x), "f"(v.y), "f"(v.z), "f"(v.w)
                 : "memory");
}

// ---------------------------------------------------------------------------
// s2 Kernel: x_gemm — out[n] = x[n] @ W1^T + b   (K = 64, W1 = W[:, :64])
// 64 nodes x 64 outs per 256-thread block; thread = 1 node x 16 outs.
// smem = 33.0 KB (< 48 KB default).
// ---------------------------------------------------------------------------
#define XF_STRIDE 65
#define XG_SMEM ((64 * 64 + 64 * XF_STRIDE) * 4)

__global__ void __launch_bounds__(256)
x_gemm_kernel(const float* __restrict__ x,
              const float* __restrict__ b,
              float* __restrict__ out) {
    extern __shared__ float sm[];
    float* Wt = sm;                 // [k][o] k=0..63, stride 64
    float* F  = sm + 64 * 64;       // [c][n] stride 65

    int t = threadIdx.x;
    int base = blockIdx.x * 64;

    #pragma unroll
    for (int i = t; i < 64 * 64 / 4; i += 256)
        ((float4*)Wt)[i] = ((const float4*)g_Wt)[i];     // rows 0..63

    #pragma unroll
    for (int i = t; i < 64 * 64; i += 256) {
        int nl = i >> 6;
        int c  = i & 63;
        int n  = base + nl;
        F[c * XF_STRIDE + nl] = (n < NUM_NODES) ? x[n * C + c] : 0.f;
    }
    __syncthreads();

    int nl = t & 63;
    int o0 = (t >> 6) << 4;   // 0,16,32,48 (warp-uniform)
    int n  = base + nl;

    unsigned long long acc[8];
    #pragma unroll
    for (int p = 0; p < 8; p++) acc[p] = 0ULL;

    const float* frow = F + nl;
    const float* wrow = Wt + o0;

    #pragma unroll 8
    for (int k = 0; k < 64; k++) {
        float f = frow[k * XF_STRIDE];
        unsigned long long fp;
        asm("mov.b64 %0, {%1, %1};" : "=l"(fp) : "f"(f));
        const ulonglong2* wv = (const ulonglong2*)(wrow + k * 64);
        ulonglong2 w01 = wv[0];
        ulonglong2 w23 = wv[1];
        ulonglong2 w45 = wv[2];
        ulonglong2 w67 = wv[3];
        asm("fma.rn.f32x2 %0, %1, %2, %0;" : "+l"(acc[0]) : "l"(w01.x), "l"(fp));
        asm("fma.rn.f32x2 %0, %1, %2, %0;" : "+l"(acc[1]) : "l"(w01.y), "l"(fp));
        asm("fma.rn.f32x2 %0, %1, %2, %0;" : "+l"(acc[2]) : "l"(w23.x), "l"(fp));
        asm("fma.rn.f32x2 %0, %1, %2, %0;" : "+l"(acc[3]) : "l"(w23.y), "l"(fp));
        asm("fma.rn.f32x2 %0, %1, %2, %0;" : "+l"(acc[4]) : "l"(w45.x), "l"(fp));
        asm("fma.rn.f32x2 %0, %1, %2, %0;" : "+l"(acc[5]) : "l"(w45.y), "l"(fp));
        asm("fma.rn.f32x2 %0, %1, %2, %0;" : "+l"(acc[6]) : "l"(w67.x), "l"(fp));
        asm("fma.rn.f32x2 %0, %1, %2, %0;" : "+l"(acc[7]) : "l"(w67.y), "l"(fp));
    }

    if (n >= NUM_NODES) return;

    float* orow = out + n * C + o0;
    #pragma unroll
    for (int j = 0; j < 4; j++) {
        float lo0, hi0, lo1, hi1;
        asm("mov.b64 {%0, %1}, %2;" : "=f"(lo0), "=f"(hi0) : "l"(acc[2 * j]));
        asm("mov.b64 {%0, %1}, %2;" : "=f"(lo1), "=f"(hi1) : "l"(acc[2 * j + 1]));
        float4 r;
        r.x = lo0 + b[o0 + 4 * j + 0];
        r.y = hi0 + b[o0 + 4 * j + 1];
        r.z = lo1 + b[o0 + 4 * j + 2];
        r.w = hi1 + b[o0 + 4 * j + 3];
        *(float4*)(orow + 4 * j) = r;
    }
}

// ---------------------------------------------------------------------------
// Kernel: aggr_gemm — out[n] += (aggr[n]*rdeg) @ W2^T   (K = 64, W2 = W[:, 64:])
// ---------------------------------------------------------------------------
#define AG_SMEM ((64 * 64 + 64 * XF_STRIDE + 64) * 4)

__global__ void __launch_bounds__(256)
aggr_gemm_kernel(float* __restrict__ out) {
    extern __shared__ float sm[];
    float* Wt   = sm;                          // [k][o] k=64..127
    float* F    = sm + 64 * 64;                // [c][n] stride 65
    float* rdeg = sm + 64 * 64 + 64 * XF_STRIDE;

    int t = threadIdx.x;
    int base = blockIdx.x * 64;

    #pragma unroll
    for (int i = t; i < 64 * 64 / 4; i += 256)
        ((float4*)Wt)[i] = ((const float4*)(g_Wt + 64 * 64))[i];  // rows 64..127

    if (t < 64) {
        int n = base + t;
        rdeg[t] = (n < NUM_NODES) ? __frcp_rn(fmaxf(g_deg[n], 1.0f)) : 0.0f;
    }
    __syncthreads();

    #pragma unroll
    for (int i = t; i < 64 * 64; i += 256) {
        int nl = i >> 6;
        int c  = i & 63;
        int n  = base + nl;
        F[c * XF_STRIDE + nl] = (n < NUM_NODES) ? g_aggr[n * C + c] * rdeg[nl] : 0.f;
    }
    __syncthreads();

    int nl = t & 63;
    int o0 = (t >> 6) << 4;
    int n  = base + nl;

    unsigned long long acc[8];
    #pragma unroll
    for (int p = 0; p < 8; p++) acc[p] = 0ULL;

    const float* frow = F + nl;
    const float* wrow = Wt + o0;

    #pragma unroll 8
    for (int k = 0; k < 64; k++) {
        float f = frow[k * XF_STRIDE];
        unsigned long long fp;
        asm("mov.b64 %0, {%1, %1};" : "=l"(fp) : "f"(f));
        const ulonglong2* wv = (const ulonglong2*)(wrow + k * 64);
        ulonglong2 w01 = wv[0];
        ulonglong2 w23 = wv[1];
        ulonglong2 w45 = wv[2];
        ulonglong2 w67 = wv[3];
        asm("fma.rn.f32x2 %0, %1, %2, %0;" : "+l"(acc[0]) : "l"(w01.x), "l"(fp));
        asm("fma.rn.f32x2 %0, %1, %2, %0;" : "+l"(acc[1]) : "l"(w01.y), "l"(fp));
        asm("fma.rn.f32x2 %0, %1, %2, %0;" : "+l"(acc[2]) : "l"(w23.x), "l"(fp));
        asm("fma.rn.f32x2 %0, %1, %2, %0;" : "+l"(acc[3]) : "l"(w23.y), "l"(fp));
        asm("fma.rn.f32x2 %0, %1, %2, %0;" : "+l"(acc[4]) : "l"(w45.x), "l"(fp));
        asm("fma.rn.f32x2 %0, %1, %2, %0;" : "+l"(acc[5]) : "l"(w45.y), "l"(fp));
        asm("fma.rn.f32x2 %0, %1, %2, %0;" : "+l"(acc[6]) : "l"(w67.x), "l"(fp));
        asm("fma.rn.f32x2 %0, %1, %2, %0;" : "+l"(acc[7]) : "l"(w67.y), "l"(fp));
    }

    if (n >= NUM_NODES) return;

    float* orow = out + n * C + o0;
    #pragma unroll
    for (int j = 0; j < 4; j++) {
        float lo0, hi0, lo1, hi1;
        asm("mov.b64 {%0, %1}, %2;" : "=f"(lo0), "=f"(hi0) : "l"(acc[2 * j]));
        asm("mov.b64 {%0, %1}, %2;" : "=f"(lo1), "=f"(hi1) : "l"(acc[2 * j + 1]));
        float4 r = *(float4*)(orow + 4 * j);
        r.x += lo0; r.y += hi0; r.z += lo1; r.w += hi1;
        *(float4*)(orow + 4 * j) = r;
    }
}

// ---------------------------------------------------------------------------
extern "C" void kernel_launch(void* const* d_in, const int* in_sizes, int n_in,
                              void* d_out, int out_size) {
    const float* x   = (const float*)d_in[0];
    const void*  ei  = d_in[1];
    const float* W   = (const float*)d_in[2];
    const float* b   = (const float*)d_in[3];
    float*       out = (float*)d_out;

    // Host-side resources created once (no device allocation involved).
    static cudaStream_t s2 = nullptr;
    static cudaEvent_t ev_fork = nullptr, ev_join = nullptr;
    if (s2 == nullptr) {
        cudaStreamCreateWithFlags(&s2, cudaStreamNonBlocking);
        cudaEventCreateWithFlags(&ev_fork, cudaEventDisableTiming);
        cudaEventCreateWithFlags(&ev_join, cudaEventDisableTiming);
    }

    void* aggr_ptr = nullptr;
    void* deg_ptr  = nullptr;
    cudaGetSymbolAddress(&aggr_ptr, g_aggr);
    cudaGetSymbolAddress(&deg_ptr, g_deg);

    // Main chain: zero -> pack -> scatter
    cudaMemsetAsync(deg_ptr, 0, NUM_NODES * sizeof(float));
    cudaMemsetAsync(aggr_ptr, 0, NUM_NODES * C * sizeof(float));

    // Fork s2: wprep -> x_gemm, concurrent with pack+scatter.
    cudaEventRecord(ev_fork, 0);
    cudaStreamWaitEvent(s2, ev_fork, 0);
    wprep_kernel<<<32, 256, 0, s2>>>(W);
    x_gemm_kernel<<<(NUM_NODES + 63) / 64, 256, XG_SMEM, s2>>>(x, b, out);
    cudaEventRecord(ev_join, s2);

    pack_kernel<<<HALF_E / 640, 640>>>(ei);
    scatter_kernel<<<(NUM_EDGES * 16) / 256, 256>>>(x);

    // Join: aggr_gemm needs scatter (main) + wprep/x_gemm (s2).
    cudaStreamWaitEvent(0, ev_join, 0);
    aggr_gemm_kernel<<<(NUM_NODES + 63) / 64, 256, AG_SMEM>>>(out);
}

// round 12
// speedup vs baseline: 1.1758x; 1.0222x over previous
#include <cuda_runtime.h>

#define NUM_NODES 50000
#define C 64
#define NUM_EDGES 800000
#define HALF_E (NUM_EDGES / 2)

// Scratch (allocation-free rule: __device__ globals)
// One extra trash row: invalid edges RED into it harmlessly.
__device__ __align__(16) float g_aggr[(NUM_NODES + 1) * C];
__device__ float g_deg[NUM_NODES];
__device__ __align__(16) float g_Wt[128 * 64];    // W transposed: [k][o]
__device__ __align__(16) int2 g_edges[NUM_EDGES]; // {row*256, col*256} byte offsets

// ---------------------------------------------------------------------------
// s2 Kernel: transpose W [o][k] -> g_Wt [k][o]. 32 blocks x 256.
// ---------------------------------------------------------------------------
__global__ void wprep_kernel(const float* __restrict__ W) {
    int i = blockIdx.x * 256 + threadIdx.x;
    if (i < 64 * 128) {
        int o = i >> 7;
        int k = i & 127;
        g_Wt[k * 64 + o] = W[i];
    }
}

// ---------------------------------------------------------------------------
// Kernel: PACK (vectorized, 2 edges/thread). Per-block dtype detect via
// int64 view of the row half (in-bounds for both widths). Grid 625 x 640.
// ---------------------------------------------------------------------------
__global__ void pack_kernel(const void* __restrict__ ei_raw) {
    int t = blockIdx.x * 640 + threadIdx.x;   // [0, HALF_E)

    const long long* ei64 = (const long long*)ei_raw;
    longlong2 rv = __ldg((const longlong2*)ei64 + t);   // edges 2t, 2t+1 row half
    bool in0 = (rv.x >= 0 && rv.x < NUM_NODES);
    bool in1 = (rv.y >= 0 && rv.y < NUM_NODES);
    int is64 = __syncthreads_and(in0 && in1);

    long long r0, r1, c0, c1;
    if (is64) {
        r0 = rv.x; r1 = rv.y;
        longlong2 cv = __ldg((const longlong2*)(ei64 + NUM_EDGES) + t);
        c0 = cv.x; c1 = cv.y;
    } else {
        const int* ei = (const int*)ei_raw;
        int2 rv32 = __ldg((const int2*)ei + t);
        r0 = rv32.x; r1 = rv32.y;
        int2 cv32 = __ldg((const int2*)(ei + NUM_EDGES) + t);
        c0 = cv32.x; c1 = cv32.y;
    }
    bool ok0 = (r0 >= 0 && r0 < NUM_NODES && c0 >= 0 && c0 < NUM_NODES);
    bool ok1 = (r1 >= 0 && r1 < NUM_NODES && c1 >= 0 && c1 < NUM_NODES);

    int4 pk;
    pk.x = ok0 ? (int)r0 * 256 : 0;
    pk.y = ok0 ? (int)c0 * 256 : NUM_NODES * 256;
    pk.z = ok1 ? (int)r1 * 256 : 0;
    pk.w = ok1 ? (int)c1 * 256 : NUM_NODES * 256;
    ((int4*)g_edges)[t] = pk;

    if (ok0) atomicAdd(&g_deg[(int)c0], 1.0f);
    if (ok1) atomicAdd(&g_deg[(int)c1], 1.0f);
}

// ---------------------------------------------------------------------------
// Kernel: PAIRED slim scatter — 16 lanes per edge-PAIR. One broadcast int4
// (both edges' offsets), then 2 independent LDG.128 + 2 RED.128 -> MLP=2.
// Branch-free (pack routed invalid edges to the trash row).
// Grid exact: HALF_E * 16 / 256 = 25000.
// ---------------------------------------------------------------------------
__global__ void scatter_kernel(const float* __restrict__ x) {
    int idx = blockIdx.x * 256 + threadIdx.x;
    int p     = idx >> 4;        // pair index [0, HALF_E)
    int chunk = idx & 15;

    int4 off = __ldg(((const int4*)g_edges) + p);   // 16 lanes same addr

    float4 v0 = __ldg((const float4*)((const char*)x + off.x) + chunk);
    float4 v1 = __ldg((const float4*)((const char*)x + off.z) + chunk);

    float* dst0 = (float*)((char*)g_aggr + off.y) + (chunk << 2);
    float* dst1 = (float*)((char*)g_aggr + off.w) + (chunk << 2);
    asm volatile("red.global.add.v4.f32 [%0], {%1,%2,%3,%4};"
                 :: "l"(dst0), "f"(v0.x), "f"(v0.y), "f"(v0.z), "f"(v0.w)
                 : "memory");
    asm volatile("red.global.add.v4.f32 [%0], {%1,%2,%3,%4};"
                 :: "l"(dst1), "f"(v1.x), "f"(v1.y), "f"(v1.z), "f"(v1.w)
                 : "memory");
}

// ---------------------------------------------------------------------------
// s2 Kernel: x_gemm — out[n] = x[n] @ W1^T + b   (K = 64, W1 = W[:, :64])
// ---------------------------------------------------------------------------
#define XF_STRIDE 65
#define XG_SMEM ((64 * 64 + 64 * XF_STRIDE) * 4)

__global__ void __launch_bounds__(256)
x_gemm_kernel(const float* __restrict__ x,
              const float* __restrict__ b,
              float* __restrict__ out) {
    extern __shared__ float sm[];
    float* Wt = sm;                 // [k][o] k=0..63, stride 64
    float* F  = sm + 64 * 64;       // [c][n] stride 65

    int t = threadIdx.x;
    int base = blockIdx.x * 64;

    #pragma unroll
    for (int i = t; i < 64 * 64 / 4; i += 256)
        ((float4*)Wt)[i] = ((const float4*)g_Wt)[i];     // rows 0..63

    #pragma unroll
    for (int i = t; i < 64 * 64; i += 256) {
        int nl = i >> 6;
        int c  = i & 63;
        int n  = base + nl;
        F[c * XF_STRIDE + nl] = (n < NUM_NODES) ? x[n * C + c] : 0.f;
    }
    __syncthreads();

    int nl = t & 63;
    int o0 = (t >> 6) << 4;   // 0,16,32,48 (warp-uniform)
    int n  = base + nl;

    unsigned long long acc[8];
    #pragma unroll
    for (int p = 0; p < 8; p++) acc[p] = 0ULL;

    const float* frow = F + nl;
    const float* wrow = Wt + o0;

    #pragma unroll 8
    for (int k = 0; k < 64; k++) {
        float f = frow[k * XF_STRIDE];
        unsigned long long fp;
        asm("mov.b64 %0, {%1, %1};" : "=l"(fp) : "f"(f));
        const ulonglong2* wv = (const ulonglong2*)(wrow + k * 64);
        ulonglong2 w01 = wv[0];
        ulonglong2 w23 = wv[1];
        ulonglong2 w45 = wv[2];
        ulonglong2 w67 = wv[3];
        asm("fma.rn.f32x2 %0, %1, %2, %0;" : "+l"(acc[0]) : "l"(w01.x), "l"(fp));
        asm("fma.rn.f32x2 %0, %1, %2, %0;" : "+l"(acc[1]) : "l"(w01.y), "l"(fp));
        asm("fma.rn.f32x2 %0, %1, %2, %0;" : "+l"(acc[2]) : "l"(w23.x), "l"(fp));
        asm("fma.rn.f32x2 %0, %1, %2, %0;" : "+l"(acc[3]) : "l"(w23.y), "l"(fp));
        asm("fma.rn.f32x2 %0, %1, %2, %0;" : "+l"(acc[4]) : "l"(w45.x), "l"(fp));
        asm("fma.rn.f32x2 %0, %1, %2, %0;" : "+l"(acc[5]) : "l"(w45.y), "l"(fp));
        asm("fma.rn.f32x2 %0, %1, %2, %0;" : "+l"(acc[6]) : "l"(w67.x), "l"(fp));
        asm("fma.rn.f32x2 %0, %1, %2, %0;" : "+l"(acc[7]) : "l"(w67.y), "l"(fp));
    }

    if (n >= NUM_NODES) return;

    float* orow = out + n * C + o0;
    #pragma unroll
    for (int j = 0; j < 4; j++) {
        float lo0, hi0, lo1, hi1;
        asm("mov.b64 {%0, %1}, %2;" : "=f"(lo0), "=f"(hi0) : "l"(acc[2 * j]));
        asm("mov.b64 {%0, %1}, %2;" : "=f"(lo1), "=f"(hi1) : "l"(acc[2 * j + 1]));
        float4 r;
        r.x = lo0 + b[o0 + 4 * j + 0];
        r.y = hi0 + b[o0 + 4 * j + 1];
        r.z = lo1 + b[o0 + 4 * j + 2];
        r.w = hi1 + b[o0 + 4 * j + 3];
        *(float4*)(orow + 4 * j) = r;
    }
}

// ---------------------------------------------------------------------------
// Kernel: aggr_gemm — out[n] += (aggr[n]*rdeg) @ W2^T   (K = 64, W2 = W[:, 64:])
// ---------------------------------------------------------------------------
#define AG_SMEM ((64 * 64 + 64 * XF_STRIDE + 64) * 4)

__global__ void __launch_bounds__(256)
aggr_gemm_kernel(float* __restrict__ out) {
    extern __shared__ float sm[];
    float* Wt   = sm;                          // [k][o] k=64..127
    float* F    = sm + 64 * 64;                // [c][n] stride 65
    float* rdeg = sm + 64 * 64 + 64 * XF_STRIDE;

    int t = threadIdx.x;
    int base = blockIdx.x * 64;

    #pragma unroll
    for (int i = t; i < 64 * 64 / 4; i += 256)
        ((float4*)Wt)[i] = ((const float4*)(g_Wt + 64 * 64))[i];  // rows 64..127

    if (t < 64) {
        int n = base + t;
        rdeg[t] = (n < NUM_NODES) ? __frcp_rn(fmaxf(g_deg[n], 1.0f)) : 0.0f;
    }
    __syncthreads();

    #pragma unroll
    for (int i = t; i < 64 * 64; i += 256) {
        int nl = i >> 6;
        int c  = i & 63;
        int n  = base + nl;
        F[c * XF_STRIDE + nl] = (n < NUM_NODES) ? g_aggr[n * C + c] * rdeg[nl] : 0.f;
    }
    __syncthreads();

    int nl = t & 63;
    int o0 = (t >> 6) << 4;
    int n  = base + nl;

    unsigned long long acc[8];
    #pragma unroll
    for (int p = 0; p < 8; p++) acc[p] = 0ULL;

    const float* frow = F + nl;
    const float* wrow = Wt + o0;

    #pragma unroll 8
    for (int k = 0; k < 64; k++) {
        float f = frow[k * XF_STRIDE];
        unsigned long long fp;
        asm("mov.b64 %0, {%1, %1};" : "=l"(fp) : "f"(f));
        const ulonglong2* wv = (const ulonglong2*)(wrow + k * 64);
        ulonglong2 w01 = wv[0];
        ulonglong2 w23 = wv[1];
        ulonglong2 w45 = wv[2];
        ulonglong2 w67 = wv[3];
        asm("fma.rn.f32x2 %0, %1, %2, %0;" : "+l"(acc[0]) : "l"(w01.x), "l"(fp));
        asm("fma.rn.f32x2 %0, %1, %2, %0;" : "+l"(acc[1]) : "l"(w01.y), "l"(fp));
        asm("fma.rn.f32x2 %0, %1, %2, %0;" : "+l"(acc[2]) : "l"(w23.x), "l"(fp));
        asm("fma.rn.f32x2 %0, %1, %2, %0;" : "+l"(acc[3]) : "l"(w23.y), "l"(fp));
        asm("fma.rn.f32x2 %0, %1, %2, %0;" : "+l"(acc[4]) : "l"(w45.x), "l"(fp));
        asm("fma.rn.f32x2 %0, %1, %2, %0;" : "+l"(acc[5]) : "l"(w45.y), "l"(fp));
        asm("fma.rn.f32x2 %0, %1, %2, %0;" : "+l"(acc[6]) : "l"(w67.x), "l"(fp));
        asm("fma.rn.f32x2 %0, %1, %2, %0;" : "+l"(acc[7]) : "l"(w67.y), "l"(fp));
    }

    if (n >= NUM_NODES) return;

    float* orow = out + n * C + o0;
    #pragma unroll
    for (int j = 0; j < 4; j++) {
        float lo0, hi0, lo1, hi1;
        asm("mov.b64 {%0, %1}, %2;" : "=f"(lo0), "=f"(hi0) : "l"(acc[2 * j]));
        asm("mov.b64 {%0, %1}, %2;" : "=f"(lo1), "=f"(hi1) : "l"(acc[2 * j + 1]));
        float4 r = *(float4*)(orow + 4 * j);
        r.x += lo0; r.y += hi0; r.z += lo1; r.w += hi1;
        *(float4*)(orow + 4 * j) = r;
    }
}

// ---------------------------------------------------------------------------
extern "C" void kernel_launch(void* const* d_in, const int* in_sizes, int n_in,
                              void* d_out, int out_size) {
    const float* x   = (const float*)d_in[0];
    const void*  ei  = d_in[1];
    const float* W   = (const float*)d_in[2];
    const float* b   = (const float*)d_in[3];
    float*       out = (float*)d_out;

    // Host-side resources created once (no device allocation involved).
    static cudaStream_t s2 = nullptr;
    static cudaEvent_t ev_fork = nullptr, ev_aggr = nullptr, ev_join = nullptr;
    if (s2 == nullptr) {
        cudaStreamCreateWithFlags(&s2, cudaStreamNonBlocking);
        cudaEventCreateWithFlags(&ev_fork, cudaEventDisableTiming);
        cudaEventCreateWithFlags(&ev_aggr, cudaEventDisableTiming);
        cudaEventCreateWithFlags(&ev_join, cudaEventDisableTiming);
    }

    void* aggr_ptr = nullptr;
    void* deg_ptr  = nullptr;
    cudaGetSymbolAddress(&aggr_ptr, g_aggr);
    cudaGetSymbolAddress(&deg_ptr, g_deg);

    // Main: memset(deg) -> pack   (pack needs deg zeroed)
    cudaMemsetAsync(deg_ptr, 0, NUM_NODES * sizeof(float));

    // Fork s2: memset(aggr) -> wprep -> x_gemm, concurrent with pack.
    cudaEventRecord(ev_fork, 0);
    cudaStreamWaitEvent(s2, ev_fork, 0);
    cudaMemsetAsync(aggr_ptr, 0, NUM_NODES * C * sizeof(float), s2);
    cudaEventRecord(ev_aggr, s2);
    wprep_kernel<<<32, 256, 0, s2>>>(W);
    x_gemm_kernel<<<(NUM_NODES + 63) / 64, 256, XG_SMEM, s2>>>(x, b, out);
    cudaEventRecord(ev_join, s2);

    pack_kernel<<<HALF_E / 640, 640>>>(ei);

    // Scatter needs aggr zeroed (s2) + pack (main).
    cudaStreamWaitEvent(0, ev_aggr, 0);
    scatter_kernel<<<(HALF_E * 16) / 256, 256>>>(x);

    // Join: aggr_gemm needs scatter (main) + wprep/x_gemm (s2).
    cudaStreamWaitEvent(0, ev_join, 0);
    aggr_gemm_kernel<<<(NUM_NODES + 63) / 64, 256, AG_SMEM>>>(out);
}

// round 13
// speedup vs baseline: 1.2035x; 1.0235x over previous
#include <cuda_runtime.h>

#define NUM_NODES 50000
#define C 64
#define NUM_EDGES 800000
#define HALF_E (NUM_EDGES / 2)
#define QUAD_E (NUM_EDGES / 4)

// Scratch (allocation-free rule: __device__ globals)
// One extra trash row: invalid edges RED into it harmlessly.
__device__ __align__(16) float g_aggr[(NUM_NODES + 1) * C];
__device__ float g_deg[NUM_NODES];
__device__ __align__(16) float g_Wt[128 * 64];    // W transposed: [k][o]
__device__ __align__(16) int2 g_edges[NUM_EDGES]; // {row*256, col*256} byte offsets

// ---------------------------------------------------------------------------
// s2 Kernel: transpose W [o][k] -> g_Wt [k][o]. 32 blocks x 256.
// ---------------------------------------------------------------------------
__global__ void wprep_kernel(const float* __restrict__ W) {
    int i = blockIdx.x * 256 + threadIdx.x;
    if (i < 64 * 128) {
        int o = i >> 7;
        int k = i & 127;
        g_Wt[k * 64 + o] = W[i];
    }
}

// ---------------------------------------------------------------------------
// Kernel: PACK (vectorized, 2 edges/thread). Per-block dtype detect via
// int64 view of the row half (in-bounds for both widths). Grid 625 x 640.
// ---------------------------------------------------------------------------
__global__ void pack_kernel(const void* __restrict__ ei_raw) {
    int t = blockIdx.x * 640 + threadIdx.x;   // [0, HALF_E)

    const long long* ei64 = (const long long*)ei_raw;
    longlong2 rv = __ldg((const longlong2*)ei64 + t);   // edges 2t, 2t+1 row half
    bool in0 = (rv.x >= 0 && rv.x < NUM_NODES);
    bool in1 = (rv.y >= 0 && rv.y < NUM_NODES);
    int is64 = __syncthreads_and(in0 && in1);

    long long r0, r1, c0, c1;
    if (is64) {
        r0 = rv.x; r1 = rv.y;
        longlong2 cv = __ldg((const longlong2*)(ei64 + NUM_EDGES) + t);
        c0 = cv.x; c1 = cv.y;
    } else {
        const int* ei = (const int*)ei_raw;
        int2 rv32 = __ldg((const int2*)ei + t);
        r0 = rv32.x; r1 = rv32.y;
        int2 cv32 = __ldg((const int2*)(ei + NUM_EDGES) + t);
        c0 = cv32.x; c1 = cv32.y;
    }
    bool ok0 = (r0 >= 0 && r0 < NUM_NODES && c0 >= 0 && c0 < NUM_NODES);
    bool ok1 = (r1 >= 0 && r1 < NUM_NODES && c1 >= 0 && c1 < NUM_NODES);

    int4 pk;
    pk.x = ok0 ? (int)r0 * 256 : 0;
    pk.y = ok0 ? (int)c0 * 256 : NUM_NODES * 256;
    pk.z = ok1 ? (int)r1 * 256 : 0;
    pk.w = ok1 ? (int)c1 * 256 : NUM_NODES * 256;
    ((int4*)g_edges)[t] = pk;

    if (ok0) atomicAdd(&g_deg[(int)c0], 1.0f);
    if (ok1) atomicAdd(&g_deg[(int)c1], 1.0f);
}

// ---------------------------------------------------------------------------
// Kernel: QUAD slim scatter — 16 lanes per 4-edge group. Two broadcast int4
// loads (4 edges' offsets), then 4 independent LDG.128 + 4 RED.128 -> MLP=4.
// Branch-free; lane layout stays 16 lanes per 256B row (validated).
// Grid exact: QUAD_E * 16 / 256 = 12500.
// ---------------------------------------------------------------------------
__global__ void scatter_kernel(const float* __restrict__ x) {
    int idx = blockIdx.x * 256 + threadIdx.x;
    int q     = idx >> 4;        // quad index [0, QUAD_E)
    int chunk = idx & 15;

    const int4* eq = (const int4*)g_edges;
    int4 o01 = __ldg(eq + 2 * q);       // edges 4q, 4q+1
    int4 o23 = __ldg(eq + 2 * q + 1);   // edges 4q+2, 4q+3

    float4 v0 = __ldg((const float4*)((const char*)x + o01.x) + chunk);
    float4 v1 = __ldg((const float4*)((const char*)x + o01.z) + chunk);
    float4 v2 = __ldg((const float4*)((const char*)x + o23.x) + chunk);
    float4 v3 = __ldg((const float4*)((const char*)x + o23.z) + chunk);

    float* dst0 = (float*)((char*)g_aggr + o01.y) + (chunk << 2);
    float* dst1 = (float*)((char*)g_aggr + o01.w) + (chunk << 2);
    float* dst2 = (float*)((char*)g_aggr + o23.y) + (chunk << 2);
    float* dst3 = (float*)((char*)g_aggr + o23.w) + (chunk << 2);
    asm volatile("red.global.add.v4.f32 [%0], {%1,%2,%3,%4};"
                 :: "l"(dst0), "f"(v0.x), "f"(v0.y), "f"(v0.z), "f"(v0.w) : "memory");
    asm volatile("red.global.add.v4.f32 [%0], {%1,%2,%3,%4};"
                 :: "l"(dst1), "f"(v1.x), "f"(v1.y), "f"(v1.z), "f"(v1.w) : "memory");
    asm volatile("red.global.add.v4.f32 [%0], {%1,%2,%3,%4};"
                 :: "l"(dst2), "f"(v2.x), "f"(v2.y), "f"(v2.z), "f"(v2.w) : "memory");
    asm volatile("red.global.add.v4.f32 [%0], {%1,%2,%3,%4};"
                 :: "l"(dst3), "f"(v3.x), "f"(v3.y), "f"(v3.z), "f"(v3.w) : "memory");
}

// ---------------------------------------------------------------------------
// s2 Kernel: x_gemm — out[n] = x[n] @ W1^T + b   (K = 64, W1 = W[:, :64])
// ---------------------------------------------------------------------------
#define XF_STRIDE 65
#define XG_SMEM ((64 * 64 + 64 * XF_STRIDE) * 4)

__global__ void __launch_bounds__(256)
x_gemm_kernel(const float* __restrict__ x,
              const float* __restrict__ b,
              float* __restrict__ out) {
    extern __shared__ float sm[];
    float* Wt = sm;                 // [k][o] k=0..63, stride 64
    float* F  = sm + 64 * 64;       // [c][n] stride 65

    int t = threadIdx.x;
    int base = blockIdx.x * 64;

    #pragma unroll
    for (int i = t; i < 64 * 64 / 4; i += 256)
        ((float4*)Wt)[i] = ((const float4*)g_Wt)[i];     // rows 0..63

    #pragma unroll
    for (int i = t; i < 64 * 64; i += 256) {
        int nl = i >> 6;
        int c  = i & 63;
        int n  = base + nl;
        F[c * XF_STRIDE + nl] = (n < NUM_NODES) ? x[n * C + c] : 0.f;
    }
    __syncthreads();

    int nl = t & 63;
    int o0 = (t >> 6) << 4;   // 0,16,32,48 (warp-uniform)
    int n  = base + nl;

    unsigned long long acc[8];
    #pragma unroll
    for (int p = 0; p < 8; p++) acc[p] = 0ULL;

    const float* frow = F + nl;
    const float* wrow = Wt + o0;

    #pragma unroll 8
    for (int k = 0; k < 64; k++) {
        float f = frow[k * XF_STRIDE];
        unsigned long long fp;
        asm("mov.b64 %0, {%1, %1};" : "=l"(fp) : "f"(f));
        const ulonglong2* wv = (const ulonglong2*)(wrow + k * 64);
        ulonglong2 w01 = wv[0];
        ulonglong2 w23 = wv[1];
        ulonglong2 w45 = wv[2];
        ulonglong2 w67 = wv[3];
        asm("fma.rn.f32x2 %0, %1, %2, %0;" : "+l"(acc[0]) : "l"(w01.x), "l"(fp));
        asm("fma.rn.f32x2 %0, %1, %2, %0;" : "+l"(acc[1]) : "l"(w01.y), "l"(fp));
        asm("fma.rn.f32x2 %0, %1, %2, %0;" : "+l"(acc[2]) : "l"(w23.x), "l"(fp));
        asm("fma.rn.f32x2 %0, %1, %2, %0;" : "+l"(acc[3]) : "l"(w23.y), "l"(fp));
        asm("fma.rn.f32x2 %0, %1, %2, %0;" : "+l"(acc[4]) : "l"(w45.x), "l"(fp));
        asm("fma.rn.f32x2 %0, %1, %2, %0;" : "+l"(acc[5]) : "l"(w45.y), "l"(fp));
        asm("fma.rn.f32x2 %0, %1, %2, %0;" : "+l"(acc[6]) : "l"(w67.x), "l"(fp));
        asm("fma.rn.f32x2 %0, %1, %2, %0;" : "+l"(acc[7]) : "l"(w67.y), "l"(fp));
    }

    if (n >= NUM_NODES) return;

    float* orow = out + n * C + o0;
    #pragma unroll
    for (int j = 0; j < 4; j++) {
        float lo0, hi0, lo1, hi1;
        asm("mov.b64 {%0, %1}, %2;" : "=f"(lo0), "=f"(hi0) : "l"(acc[2 * j]));
        asm("mov.b64 {%0, %1}, %2;" : "=f"(lo1), "=f"(hi1) : "l"(acc[2 * j + 1]));
        float4 r;
        r.x = lo0 + b[o0 + 4 * j + 0];
        r.y = hi0 + b[o0 + 4 * j + 1];
        r.z = lo1 + b[o0 + 4 * j + 2];
        r.w = hi1 + b[o0 + 4 * j + 3];
        *(float4*)(orow + 4 * j) = r;
    }
}

// ---------------------------------------------------------------------------
// Kernel: aggr_gemm — out[n] += (aggr[n]*rdeg) @ W2^T   (K = 64, W2 = W[:, 64:])
// ---------------------------------------------------------------------------
#define AG_SMEM ((64 * 64 + 64 * XF_STRIDE + 64) * 4)

__global__ void __launch_bounds__(256)
aggr_gemm_kernel(float* __restrict__ out) {
    extern __shared__ float sm[];
    float* Wt   = sm;                          // [k][o] k=64..127
    float* F    = sm + 64 * 64;                // [c][n] stride 65
    float* rdeg = sm + 64 * 64 + 64 * XF_STRIDE;

    int t = threadIdx.x;
    int base = blockIdx.x * 64;

    #pragma unroll
    for (int i = t; i < 64 * 64 / 4; i += 256)
        ((float4*)Wt)[i] = ((const float4*)(g_Wt + 64 * 64))[i];  // rows 64..127

    if (t < 64) {
        int n = base + t;
        rdeg[t] = (n < NUM_NODES) ? __frcp_rn(fmaxf(g_deg[n], 1.0f)) : 0.0f;
    }
    __syncthreads();

    #pragma unroll
    for (int i = t; i < 64 * 64; i += 256) {
        int nl = i >> 6;
        int c  = i & 63;
        int n  = base + nl;
        F[c * XF_STRIDE + nl] = (n < NUM_NODES) ? g_aggr[n * C + c] * rdeg[nl] : 0.f;
    }
    __syncthreads();

    int nl = t & 63;
    int o0 = (t >> 6) << 4;
    int n  = base + nl;

    unsigned long long acc[8];
    #pragma unroll
    for (int p = 0; p < 8; p++) acc[p] = 0ULL;

    const float* frow = F + nl;
    const float* wrow = Wt + o0;

    #pragma unroll 8
    for (int k = 0; k < 64; k++) {
        float f = frow[k * XF_STRIDE];
        unsigned long long fp;
        asm("mov.b64 %0, {%1, %1};" : "=l"(fp) : "f"(f));
        const ulonglong2* wv = (const ulonglong2*)(wrow + k * 64);
        ulonglong2 w01 = wv[0];
        ulonglong2 w23 = wv[1];
        ulonglong2 w45 = wv[2];
        ulonglong2 w67 = wv[3];
        asm("fma.rn.f32x2 %0, %1, %2, %0;" : "+l"(acc[0]) : "l"(w01.x), "l"(fp));
        asm("fma.rn.f32x2 %0, %1, %2, %0;" : "+l"(acc[1]) : "l"(w01.y), "l"(fp));
        asm("fma.rn.f32x2 %0, %1, %2, %0;" : "+l"(acc[2]) : "l"(w23.x), "l"(fp));
        asm("fma.rn.f32x2 %0, %1, %2, %0;" : "+l"(acc[3]) : "l"(w23.y), "l"(fp));
        asm("fma.rn.f32x2 %0, %1, %2, %0;" : "+l"(acc[4]) : "l"(w45.x), "l"(fp));
        asm("fma.rn.f32x2 %0, %1, %2, %0;" : "+l"(acc[5]) : "l"(w45.y), "l"(fp));
        asm("fma.rn.f32x2 %0, %1, %2, %0;" : "+l"(acc[6]) : "l"(w67.x), "l"(fp));
        asm("fma.rn.f32x2 %0, %1, %2, %0;" : "+l"(acc[7]) : "l"(w67.y), "l"(fp));
    }

    if (n >= NUM_NODES) return;

    float* orow = out + n * C + o0;
    #pragma unroll
    for (int j = 0; j < 4; j++) {
        float lo0, hi0, lo1, hi1;
        asm("mov.b64 {%0, %1}, %2;" : "=f"(lo0), "=f"(hi0) : "l"(acc[2 * j]));
        asm("mov.b64 {%0, %1}, %2;" : "=f"(lo1), "=f"(hi1) : "l"(acc[2 * j + 1]));
        float4 r = *(float4*)(orow + 4 * j);
        r.x += lo0; r.y += hi0; r.z += lo1; r.w += hi1;
        *(float4*)(orow + 4 * j) = r;
    }
}

// ---------------------------------------------------------------------------
extern "C" void kernel_launch(void* const* d_in, const int* in_sizes, int n_in,
                              void* d_out, int out_size) {
    const float* x   = (const float*)d_in[0];
    const void*  ei  = d_in[1];
    const float* W   = (const float*)d_in[2];
    const float* b   = (const float*)d_in[3];
    float*       out = (float*)d_out;

    // Host-side resources created once (no device allocation involved).
    static cudaStream_t s2 = nullptr;
    static cudaEvent_t ev_fork = nullptr, ev_aggr = nullptr, ev_join = nullptr;
    if (s2 == nullptr) {
        cudaStreamCreateWithFlags(&s2, cudaStreamNonBlocking);
        cudaEventCreateWithFlags(&ev_fork, cudaEventDisableTiming);
        cudaEventCreateWithFlags(&ev_aggr, cudaEventDisableTiming);
        cudaEventCreateWithFlags(&ev_join, cudaEventDisableTiming);
    }

    void* aggr_ptr = nullptr;
    void* deg_ptr  = nullptr;
    cudaGetSymbolAddress(&aggr_ptr, g_aggr);
    cudaGetSymbolAddress(&deg_ptr, g_deg);

    // Main: memset(deg) -> pack   (pack needs deg zeroed)
    cudaMemsetAsync(deg_ptr, 0, NUM_NODES * sizeof(float));

    // Fork s2: memset(aggr) -> wprep -> x_gemm, concurrent with pack.
    cudaEventRecord(ev_fork, 0);
    cudaStreamWaitEvent(s2, ev_fork, 0);
    cudaMemsetAsync(aggr_ptr, 0, NUM_NODES * C * sizeof(float), s2);
    cudaEventRecord(ev_aggr, s2);
    wprep_kernel<<<32, 256, 0, s2>>>(W);
    x_gemm_kernel<<<(NUM_NODES + 63) / 64, 256, XG_SMEM, s2>>>(x, b, out);
    cudaEventRecord(ev_join, s2);

    pack_kernel<<<HALF_E / 640, 640>>>(ei);

    // Scatter needs aggr zeroed (s2) + pack (main).
    cudaStreamWaitEvent(0, ev_aggr, 0);
    scatter_kernel<<<(QUAD_E * 16) / 256, 256>>>(x);

    // Join: aggr_gemm needs scatter (main) + wprep/x_gemm (s2).
    cudaStreamWaitEvent(0, ev_join, 0);
    aggr_gemm_kernel<<<(NUM_NODES + 63) / 64, 256, AG_SMEM>>>(out);
}